// round 8
// baseline (speedup 1.0000x reference)
#include <cuda_runtime.h>
#include <math.h>
#include <stdint.h>

#define B      128
#define L      196
#define DTOP   64
#define DLOW   128
#define NE     512
#define NBOOK  15
#define EPSF   1e-8f
#define INV512 (1.0f/512.0f)

#define BM        32
#define KT        8
#define NTHREADS  256
#define ROWBLOCKS 7

#define QUANT_OFF 0ll
#define QUANT_CNT (4ll*B*L*DLOW)
#define DIFF_OFF  (QUANT_OFF + QUANT_CNT)
#define ID_OFF    (DIFF_OFF + 1)
#define ID_CNT    (4ll*B*L)
#define OT_OFF    (ID_OFF + ID_CNT)

__device__ float g_q4[B*L*DTOP];
__device__ float g_e2_top[NBOOK*NE];
__device__ float g_e2_lvl[4*NBOOK*NE];
__device__ float g_inve0[NBOOK*NE];
__device__ float g_embT_top[NBOOK*NE*DTOP];
__device__ float g_embT_lvl[4*NBOOK*NE*DLOW];

__device__ __forceinline__ unsigned smem_u32(const void* p) {
    unsigned r;
    asm("{.reg .u64 t; cvta.to.shared.u64 t, %1; cvt.u32.u64 %0, t;}" : "=r"(r) : "l"(p));
    return r;
}
__device__ __forceinline__ void cp16(unsigned dst, const void* src) {
    asm volatile("cp.async.cg.shared.global [%0], [%1], 16;" :: "r"(dst), "l"(src));
}
#define CP_COMMIT() asm volatile("cp.async.commit_group;" ::: "memory")
#define CP_WAIT0()  asm volatile("cp.async.wait_group 0;" ::: "memory")
#define CP_WAIT1()  asm volatile("cp.async.wait_group 1;" ::: "memory")
#define FMA2(a,x,e) asm("fma.rn.f32x2 %0, %1, %2, %0;" : "+l"(a) : "l"(x), "l"(e))

__global__ void norms_kernel(const float* __restrict__ cb_top,
                             const float* __restrict__ cb_lvl,
                             float* __restrict__ out)
{
    int k = threadIdx.x, book = blockIdx.x;
    if (book == 0 && k == 0) out[DIFF_OFF] = 0.0f;
    if (book < NBOOK) {
        const float* e = cb_top + (size_t)book * DTOP * NE;
        float s = 0.f;
        #pragma unroll 8
        for (int i = 0; i < DTOP; ++i) { float v = e[(size_t)i*NE + k]; s += v*v; }
        g_e2_top[book*NE + k] = s;
    } else {
        int bl = book - NBOOK;
        const float* e = cb_lvl + (size_t)bl * DLOW * NE;
        float s = 0.f;
        #pragma unroll 8
        for (int i = 0; i < DLOW; ++i) { float v = e[(size_t)i*NE + k]; s += v*v; }
        g_e2_lvl[bl*NE + k] = s;
        if (bl < NBOOK) g_inve0[bl*NE + k] = 1.0f / (sqrtf(s) + EPSF);
    }
}

__global__ void transpose_kernel(const float* __restrict__ cb_top,
                                 const float* __restrict__ cb_lvl)
{
    __shared__ float tile[32][33];
    int book = blockIdx.z;
    int k0 = blockIdx.x * 32, d0 = blockIdx.y * 32;
    const float* src; float* dst; int OD;
    if (book < NBOOK) {
        if (d0 >= DTOP) return;
        src = cb_top + (size_t)book * DTOP * NE;
        dst = g_embT_top + (size_t)book * NE * DTOP;  OD = DTOP;
    } else {
        int bl = book - NBOOK;
        src = cb_lvl + (size_t)bl * DLOW * NE;
        dst = g_embT_lvl + (size_t)bl * NE * DLOW;    OD = DLOW;
    }
    int tx = threadIdx.x, ty = threadIdx.y;
    #pragma unroll
    for (int dy = ty; dy < 32; dy += 8)
        tile[dy][tx] = src[(size_t)(d0 + dy) * NE + k0 + tx];
    __syncthreads();
    #pragma unroll
    for (int dy = ty; dy < 32; dy += 8)
        dst[(size_t)(k0 + dy) * OD + d0 + tx] = tile[tx][dy];
}

__device__ __forceinline__ float load_x_low(const float* __restrict__ in,
                                            int j, int b, int l, int c)
{
    if (c < DTOP) return in[((((size_t)j*B + b)*L + l)*DTOP) + c];
    return g_q4[(((size_t)b*L + l)*DTOP) + (c - DTOP)];
}
__device__ __forceinline__ float load_x_top(const float* __restrict__ in,
                                            int b, int l, int c)
{
    return in[((((size_t)4*B + b)*L + l)*DTOP) + c];
}

struct Epi {
    float minv[8][BM]; int mini[8][BM];
    float otm[8][BM], otz[8][BM], ott[8][BM];
    int ind[BM]; float dist[BM];
};

// small operand set: 16 regs -> 1-step pipeline fits under the 128-reg cap
struct EX { ulonglong2 ea, eb; float4 xa, xb; };

__device__ __forceinline__ void load_ex(EX& r, const char* ek, const float* xk, int i)
{
    // e chunks: permuted layout [k][w][sub][co]16B; ek already offset by w*256+co*16
    r.ea = *(const ulonglong2*)(ek + i*2048);          // sub 0: cols colb..colb+3
    r.eb = *(const ulonglong2*)(ek + i*2048 + 128);    // sub 1: cols colb+4..colb+7
    r.xa = *(const float4*)(xk + i*BM);                // rows rg8..rg8+3
    r.xb = *(const float4*)(xk + i*BM + 4);            // rows rg8+4..rg8+7
}

__device__ __forceinline__ void fma_block(unsigned long long (&acc)[8][4], const EX& v)
{
    float xr8[8] = {v.xa.x, v.xa.y, v.xa.z, v.xa.w, v.xb.x, v.xb.y, v.xb.z, v.xb.w};
    #pragma unroll
    for (int r = 0; r < 8; ++r) {
        unsigned long long xp;
        asm("mov.b64 %0, {%1,%1};" : "=l"(xp) : "f"(xr8[r]));
        FMA2(acc[r][0], xp, v.ea.x); FMA2(acc[r][1], xp, v.ea.y);
        FMA2(acc[r][2], xp, v.eb.x); FMA2(acc[r][3], xp, v.eb.y);
    }
}

// Block: 32 rows x 512 cols, 8 warps. Warp w covers cols [w*64, w*64+64).
// Lane: rg = lane>>3 (4 groups x 8 rows), co = lane&7 (8 groups x 8 cols).
template<int KDIM, bool IS_TOP>
__launch_bounds__(NTHREADS, 2)
__global__ void vq_gemm(const float* __restrict__ input_list,
                        const float* __restrict__ cb_top,
                        const float* __restrict__ cb_lvl,
                        const int*   __restrict__ label,
                        float*       __restrict__ out)
{
    __shared__ __align__(16) float e_s[2*KT*NE];    // 32 KB, permuted chunks
    __shared__ __align__(16) float x_s[KDIM*BM];    // 16/8 KB

    const int rb = blockIdx.x;
    const int b  = blockIdx.y;
    const int s  = blockIdx.z;
    const int j  = IS_TOP ? 4 : (3 - s);
    const int t  = label[b];
    const int rowbase = rb * BM;
    const int tid  = threadIdx.x;
    const int lane = tid & 31;
    const int w    = tid >> 5;         // 0..7 col band (64 cols)
    const int rg   = lane >> 3;        // 0..3, 8 rows each
    const int co   = lane & 7;         // 0..7, 8 cols each
    const int rg8  = rg * 8;
    const int colb = w * 64 + co * 8;

    const float* emb = IS_TOP ? (cb_top + (size_t)t * DTOP * NE)
                              : (cb_lvl + ((size_t)j * NBOOK + t) * DLOW * NE);
    const unsigned e_base = smem_u32(e_s);

    unsigned long long acc[8][4];   // 8 rows x 4 col-pairs
    #pragma unroll
    for (int r = 0; r < 8; ++r)
        #pragma unroll
        for (int p = 0; p < 4; ++p) acc[r][p] = 0ull;

    const int T = KDIM / KT;

    // Fill with chunk permutation: global 16B chunk gc within a 2048B k-row
    // (gc = w*16 + co*2 + sub) is stored at smem chunk sc = w*16 + sub*8 + co,
    // so a warp's LDS.128 (co 0..7, fixed sub) reads one aligned 128B span.
#define FILL_E(BUF, TILE) do {                                                 \
    const char* esrc = (const char*)(emb + (size_t)(TILE) * KT * NE);          \
    const unsigned eb_ = e_base + (BUF) * (KT*NE*4);                           \
    _Pragma("unroll")                                                          \
    for (int kk = 0; kk < 4; ++kk) {                                           \
        unsigned gct = (unsigned)(tid + kk*256);   /* chunk in tile */         \
        unsigned krow = gct >> 7, gc = gct & 127u;                             \
        unsigned sc = (gc & ~15u) | ((gc & 1u) << 3) | ((gc >> 1) & 7u);       \
        cp16(eb_ + krow*2048u + sc*16u, esrc + gct*16u);                       \
    }                                                                          \
    CP_COMMIT();                                                               \
} while (0)

#define COMPUTE(BUF) do {                                                      \
    const char* ek = (const char*)e_s + (BUF)*(KT*NE*4) + (unsigned)(w*256 + co*16); \
    EX cur, nxt;                                                               \
    load_ex(cur, ek, xk, 0);                                                   \
    _Pragma("unroll")                                                          \
    for (int i = 0; i < KT; ++i) {                                             \
        if (i + 1 < KT) load_ex(nxt, ek, xk, i + 1);                           \
        fma_block(acc, cur);                                                   \
        cur = nxt;                                                             \
    }                                                                          \
    xk += KT*BM;                                                               \
} while (0)

    FILL_E(0, 0);
    // stage x (coalesced; rows beyond L zero-padded)
    {
        const int CSHIFT = (KDIM == 128) ? 7 : 6;
        for (int it = tid; it < BM*KDIM; it += NTHREADS) {
            int row = it >> CSHIFT, c = it & (KDIM - 1);
            int l = rowbase + row;
            float v = 0.f;
            if (l < L) v = IS_TOP ? load_x_top(input_list, b, l, c)
                                  : load_x_low(input_list, j, b, l, c);
            x_s[c*BM + row] = v;
        }
    }

    const float* xk = x_s + rg8;
    for (int tt = 0; tt < T; tt += 2) {
        FILL_E(1, tt + 1);
        CP_WAIT1(); __syncthreads();      // buf0 ready
        COMPUTE(0);
        __syncthreads();                  // buf0 free
        if (tt + 2 < T) { FILL_E(0, tt + 2); CP_WAIT1(); }
        else            { CP_WAIT0(); }
        __syncthreads();                  // buf1 ready
        COMPUTE(1);
        __syncthreads();                  // buf1 free
    }

    // ---- Epilogue (aliased over dead e_s) ----
    Epi* ep = (Epi*)e_s;
    const float* e2p = IS_TOP ? (g_e2_top + (size_t)t * NE)
                              : (g_e2_lvl + ((size_t)j * NBOOK + t) * NE);
    float e2v[8];
    *(float4*)&e2v[0] = *(const float4*)&e2p[colb];
    *(float4*)&e2v[4] = *(const float4*)&e2p[colb + 4];
    const bool do_ot = (!IS_TOP) && (j == 0);
    float invev[8];
    if (do_ot) {
        const float* ip = g_inve0 + (size_t)t * NE;
        *(float4*)&invev[0] = *(const float4*)&ip[colb];
        *(float4*)&invev[4] = *(const float4*)&ip[colb + 4];
    }

    #pragma unroll
    for (int r = 0; r < 8; ++r) {
        int row = rg8 + r;
        int l = rowbase + row;

        float gv[8];
        #pragma unroll
        for (int p = 0; p < 4; ++p)
            asm("mov.b64 {%0,%1}, %2;" : "=f"(gv[2*p]), "=f"(gv[2*p+1]) : "l"(acc[r][p]));

        float bv = 3.4e38f; int bi = NE;
        #pragma unroll
        for (int c = 0; c < 8; ++c) {
            float v = fmaf(-2.f, gv[c], e2v[c]);
            if (v < bv || (v == bv && colb + c < bi)) { bv = v; bi = colb + c; }
        }
        // reduce across the 8 co lanes (same rg octet; co ascending = index ascending)
        #pragma unroll
        for (int o = 1; o <= 4; o <<= 1) {
            float ov = __shfl_xor_sync(0xffffffffu, bv, o);
            int   oi = __shfl_xor_sync(0xffffffffu, bi, o);
            if (ov < bv || (ov == bv && oi < bi)) { bv = ov; bi = oi; }
        }
        if (co == 0 && l < L) { ep->minv[w][row] = bv; ep->mini[w][row] = bi; }

        if (do_ot) {
            float m = -3.4e38f;
            #pragma unroll
            for (int c = 0; c < 8; ++c) m = fmaxf(m, gv[c] * INV512);
            #pragma unroll
            for (int o = 1; o <= 4; o <<= 1)
                m = fmaxf(m, __shfl_xor_sync(0xffffffffu, m, o));
            float Z = 0.f, Tt = 0.f;
            #pragma unroll
            for (int c = 0; c < 8; ++c) {
                float pe = expf(gv[c] * INV512 - m);
                Z += pe;  Tt += gv[c] * invev[c] * pe;
            }
            #pragma unroll
            for (int o = 1; o <= 4; o <<= 1) {
                Z  += __shfl_xor_sync(0xffffffffu, Z,  o);
                Tt += __shfl_xor_sync(0xffffffffu, Tt, o);
            }
            if (co == 0 && l < L) { ep->otm[w][row] = m; ep->otz[w][row] = Z; ep->ott[w][row] = Tt; }
        }
    }
    __syncthreads();

    // combine the 8 warp (col-band) partials per row; s2 from staged x
    if (tid < BM) {
        int row = tid, l = rowbase + row;
        if (l < L) {
            float s2 = 0.f;
            #pragma unroll 8
            for (int c = 0; c < KDIM; ++c) { float v = x_s[c*BM + row]; s2 += v*v; }
            float bv = ep->minv[0][row]; int bi = ep->mini[0][row];
            #pragma unroll
            for (int ww = 1; ww < 8; ++ww) {
                float v = ep->minv[ww][row];
                if (v < bv) { bv = v; bi = ep->mini[ww][row]; }
            }
            ep->ind[row]  = bi;
            ep->dist[row] = s2 + bv;
            if (!IS_TOP)
                out[ID_OFF + ((size_t)s*B + b)*L + l] = (float)bi;
            if (do_ot) {
                float m = ep->otm[0][row];
                #pragma unroll
                for (int ww = 1; ww < 8; ++ww) m = fmaxf(m, ep->otm[ww][row]);
                float Z = 0.f, Tt = 0.f;
                #pragma unroll
                for (int ww = 0; ww < 8; ++ww) {
                    float sc = expf(ep->otm[ww][row] - m);
                    Z  += ep->otz[ww][row] * sc;
                    Tt += ep->ott[ww][row] * sc;
                }
                float invx = 1.0f / (sqrtf(s2) + EPSF);
                out[OT_OFF + (size_t)b*L + l] = (Z - invx * Tt) / Z;
            }
        }
    }
    __syncthreads();

    if (tid == 0) {
        int nval = L - rowbase; if (nval > BM) nval = BM;
        float sum = 0.f;
        for (int r = 0; r < nval; ++r) sum += ep->dist[r];
        atomicAdd(&out[DIFF_OFF], sum * (1.0f / (float)(L * KDIM)));
    }

    const int OD = IS_TOP ? DTOP : DLOW;
    const float* embT = IS_TOP ? (g_embT_top + (size_t)t * NE * DTOP)
                               : (g_embT_lvl + ((size_t)j * NBOOK + t) * NE * DLOW);
    for (int it = tid; it < BM*OD; it += NTHREADS) {
        int r = it / OD, c = it % OD;
        int l = rowbase + r;
        if (l >= L) continue;
        float v = embT[(size_t)ep->ind[r] * OD + c];
        if (IS_TOP)
            g_q4[((size_t)b*L + l)*DTOP + c] = v;
        else
            out[QUANT_OFF + (((size_t)s*B + b)*L + l)*DLOW + c] = v;
    }
#undef FILL_E
#undef COMPUTE
}

extern "C" void kernel_launch(void* const* d_in, const int* in_sizes, int n_in,
                              void* d_out, int out_size)
{
    const float* input_list = nullptr;
    const float* cb_top     = nullptr;
    const float* cb_lvl     = nullptr;
    const int*   label      = nullptr;

    for (int i = 0; i < n_in; ++i) {
        switch (in_sizes[i]) {
            case 8028160: input_list = (const float*)d_in[i]; break;
            case 491520:  cb_top     = (const float*)d_in[i]; break;
            case 3932160: cb_lvl     = (const float*)d_in[i]; break;
            case 128:     label      = (const int*)  d_in[i]; break;
        }
    }
    if (!input_list || !cb_top || !cb_lvl || !label) return;

    float* out = (float*)d_out;

    norms_kernel<<<NBOOK + 4*NBOOK, NE>>>(cb_top, cb_lvl, out);
    transpose_kernel<<<dim3(NE/32, 4, NBOOK + 4*NBOOK), dim3(32, 8)>>>(cb_top, cb_lvl);
    vq_gemm<DTOP, true ><<<dim3(ROWBLOCKS, B, 1), NTHREADS>>>(input_list, cb_top, cb_lvl, label, out);
    vq_gemm<DLOW, false><<<dim3(ROWBLOCKS, B, 4), NTHREADS>>>(input_list, cb_top, cb_lvl, label, out);
}

// round 10
// speedup vs baseline: 1.2273x; 1.2273x over previous
#include <cuda_runtime.h>
#include <math.h>
#include <stdint.h>

#define B      128
#define L      196
#define DTOP   64
#define DLOW   128
#define NE     512
#define NBOOK  15
#define EPSF   1e-8f
#define INV512 (1.0f/512.0f)

#define BM        32
#define KT        8
#define NTHREADS  256
#define ROWBLOCKS 7

#define QUANT_OFF 0ll
#define QUANT_CNT (4ll*B*L*DLOW)
#define DIFF_OFF  (QUANT_OFF + QUANT_CNT)
#define ID_OFF    (DIFF_OFF + 1)
#define ID_CNT    (4ll*B*L)
#define OT_OFF    (ID_OFF + ID_CNT)

__device__ float g_q4[B*L*DTOP];
__device__ float g_e2_top[NBOOK*NE];
__device__ float g_e2_lvl[4*NBOOK*NE];
__device__ float g_inve0[NBOOK*NE];
__device__ float g_embT_top[NBOOK*NE*DTOP];
__device__ float g_embT_lvl[4*NBOOK*NE*DLOW];

__device__ __forceinline__ unsigned smem_u32(const void* p) {
    unsigned r;
    asm("{.reg .u64 t; cvta.to.shared.u64 t, %1; cvt.u32.u64 %0, t;}" : "=r"(r) : "l"(p));
    return r;
}
__device__ __forceinline__ void cp16(unsigned dst, const void* src) {
    asm volatile("cp.async.cg.shared.global [%0], [%1], 16;" :: "r"(dst), "l"(src));
}
#define CP_COMMIT() asm volatile("cp.async.commit_group;" ::: "memory")
#define CP_WAIT0()  asm volatile("cp.async.wait_group 0;" ::: "memory")
#define CP_WAIT1()  asm volatile("cp.async.wait_group 1;" ::: "memory")
#define FMA2(a,x,e) asm("fma.rn.f32x2 %0, %1, %2, %0;" : "+l"(a) : "l"(x), "l"(e))

__global__ void norms_kernel(const float* __restrict__ cb_top,
                             const float* __restrict__ cb_lvl,
                             float* __restrict__ out)
{
    int k = threadIdx.x, book = blockIdx.x;
    if (book == 0 && k == 0) out[DIFF_OFF] = 0.0f;
    if (book < NBOOK) {
        const float* e = cb_top + (size_t)book * DTOP * NE;
        float s = 0.f;
        #pragma unroll 8
        for (int i = 0; i < DTOP; ++i) { float v = e[(size_t)i*NE + k]; s += v*v; }
        g_e2_top[book*NE + k] = s;
    } else {
        int bl = book - NBOOK;
        const float* e = cb_lvl + (size_t)bl * DLOW * NE;
        float s = 0.f;
        #pragma unroll 8
        for (int i = 0; i < DLOW; ++i) { float v = e[(size_t)i*NE + k]; s += v*v; }
        g_e2_lvl[bl*NE + k] = s;
        if (bl < NBOOK) g_inve0[bl*NE + k] = 1.0f / (sqrtf(s) + EPSF);
    }
}

__global__ void transpose_kernel(const float* __restrict__ cb_top,
                                 const float* __restrict__ cb_lvl)
{
    __shared__ float tile[32][33];
    int book = blockIdx.z;
    int k0 = blockIdx.x * 32, d0 = blockIdx.y * 32;
    const float* src; float* dst; int OD;
    if (book < NBOOK) {
        if (d0 >= DTOP) return;
        src = cb_top + (size_t)book * DTOP * NE;
        dst = g_embT_top + (size_t)book * NE * DTOP;  OD = DTOP;
    } else {
        int bl = book - NBOOK;
        src = cb_lvl + (size_t)bl * DLOW * NE;
        dst = g_embT_lvl + (size_t)bl * NE * DLOW;    OD = DLOW;
    }
    int tx = threadIdx.x, ty = threadIdx.y;
    #pragma unroll
    for (int dy = ty; dy < 32; dy += 8)
        tile[dy][tx] = src[(size_t)(d0 + dy) * NE + k0 + tx];
    __syncthreads();
    #pragma unroll
    for (int dy = ty; dy < 32; dy += 8)
        dst[(size_t)(k0 + dy) * OD + d0 + tx] = tile[tx][dy];
}

__device__ __forceinline__ float load_x_low(const float* __restrict__ in,
                                            int j, int b, int l, int c)
{
    if (c < DTOP) return in[((((size_t)j*B + b)*L + l)*DTOP) + c];
    return g_q4[(((size_t)b*L + l)*DTOP) + (c - DTOP)];
}
__device__ __forceinline__ float load_x_top(const float* __restrict__ in,
                                            int b, int l, int c)
{
    return in[((((size_t)4*B + b)*L + l)*DTOP) + c];
}

struct Epi {
    float minv[8][BM]; int mini[8][BM];
    float otm[8][BM], otz[8][BM], ott[8][BM];
    int ind[BM]; float dist[BM];
};

// Block: 32 rows x 512 cols, 8 warps. Warp w owns cols [w*64, w*64+64) and a
// PRIVATE double-buffered e slice -> no __syncthreads in the k-loop.
// Lane: rg = lane>>3 (4 groups x 8 rows), co = lane&7 (8 groups x 8 cols).
template<int KDIM, bool IS_TOP>
__launch_bounds__(NTHREADS, 2)
__global__ void vq_gemm(const float* __restrict__ input_list,
                        const float* __restrict__ cb_top,
                        const float* __restrict__ cb_lvl,
                        const int*   __restrict__ label,
                        float*       __restrict__ out)
{
    __shared__ __align__(16) float e_s[8*2*KT*64];  // 32 KB: [w][buf][k][64c]
    __shared__ __align__(16) float x_s[KDIM*BM];    // 16/8 KB: [k][row]

    const int rb = blockIdx.x;
    const int b  = blockIdx.y;
    const int s  = blockIdx.z;
    const int j  = IS_TOP ? 4 : (3 - s);
    const int t  = label[b];
    const int rowbase = rb * BM;
    const int tid  = threadIdx.x;
    const int lane = tid & 31;
    const int w    = tid >> 5;         // 0..7 col band (64 cols)
    const int rg   = lane >> 3;        // 0..3, 8 rows each
    const int co   = lane & 7;         // 0..7, 8 cols each
    const int rg8  = rg * 8;
    const int colb = w * 64 + co * 8;

    const float* emb = IS_TOP ? (cb_top + (size_t)t * DTOP * NE)
                              : (cb_lvl + ((size_t)j * NBOOK + t) * DLOW * NE);
    const unsigned e_base = smem_u32(e_s);

    unsigned long long acc[8][4];   // 8 rows x 4 col-pairs (8 cols)
    #pragma unroll
    for (int r = 0; r < 8; ++r)
        #pragma unroll
        for (int p = 0; p < 4; ++p) acc[r][p] = 0ull;

    const int T = KDIM / KT;
    // chunk indices for this lane's 4 cp16 per fill (warp-private 2KB slice)
    const int ci_k[4]   = { lane >> 4, (lane + 32) >> 4, (lane + 64) >> 4, (lane + 96) >> 4 };
    const int ci_c16[4] = { lane & 15, lane & 15, lane & 15, lane & 15 };

    // fill warp w's slice buffer BUF with tile TILE (8k x 64 cols)
#define FILL_E(BUF, TILE) do {                                                 \
    const char* esrc = (const char*)(emb + (size_t)(TILE) * KT * NE + w * 64); \
    const unsigned dstb = e_base + (unsigned)(w*2 + (BUF)) * 2048u;            \
    _Pragma("unroll")                                                          \
    for (int q = 0; q < 4; ++q) {                                              \
        int kk = ci_k[q], c16 = ci_c16[q];                                     \
        cp16(dstb + (unsigned)(kk*256 + c16*16),                               \
             esrc + (size_t)kk*2048 + (size_t)c16*16);                         \
    }                                                                          \
    CP_COMMIT();                                                               \
} while (0)

#define COMPUTE(BUF) do {                                                      \
    const char* ek = (const char*)e_s + (unsigned)(w*2 + (BUF))*2048u + co*32; \
    _Pragma("unroll")                                                          \
    for (int i = 0; i < KT; ++i) {                                             \
        ulonglong2 ea = *(const ulonglong2*)(ek + i*256);                      \
        ulonglong2 eb = *(const ulonglong2*)(ek + i*256 + 16);                 \
        float4 xa = *(const float4*)(xk + i*BM);                               \
        float4 xb = *(const float4*)(xk + i*BM + 4);                           \
        float xr8[8] = {xa.x, xa.y, xa.z, xa.w, xb.x, xb.y, xb.z, xb.w};       \
        _Pragma("unroll")                                                      \
        for (int r = 0; r < 8; ++r) {                                          \
            unsigned long long xp;                                             \
            asm("mov.b64 %0, {%1,%1};" : "=l"(xp) : "f"(xr8[r]));              \
            FMA2(acc[r][0], xp, ea.x); FMA2(acc[r][1], xp, ea.y);              \
            FMA2(acc[r][2], xp, eb.x); FMA2(acc[r][3], xp, eb.y);              \
        }                                                                      \
    }                                                                          \
    xk += KT*BM;                                                               \
} while (0)

    FILL_E(0, 0);
    // stage x cooperatively (coalesced; pad rows zero)
    {
        const int CSHIFT = (KDIM == 128) ? 7 : 6;
        for (int it = tid; it < BM*KDIM; it += NTHREADS) {
            int row = it >> CSHIFT, c = it & (KDIM - 1);
            int l = rowbase + row;
            float v = 0.f;
            if (l < L) v = IS_TOP ? load_x_top(input_list, b, l, c)
                                  : load_x_low(input_list, j, b, l, c);
            x_s[c*BM + row] = v;
        }
    }
    __syncthreads();   // x ready for all warps

    const float* xk = x_s + rg8;
    for (int tt = 0; tt < T; ++tt) {
        if (tt + 1 < T) { FILL_E((tt + 1) & 1, tt + 1); CP_WAIT1(); }
        else            { CP_WAIT0(); }
        COMPUTE(tt & 1);
    }

    __syncthreads();   // all warps done with e_s -> safe to alias epilogue

    // ---- Epilogue (Epi aliased over dead e_s) ----
    Epi* ep = (Epi*)e_s;
    const float* e2p = IS_TOP ? (g_e2_top + (size_t)t * NE)
                              : (g_e2_lvl + ((size_t)j * NBOOK + t) * NE);
    float e2v[8];
    *(float4*)&e2v[0] = *(const float4*)&e2p[colb];
    *(float4*)&e2v[4] = *(const float4*)&e2p[colb + 4];
    const bool do_ot = (!IS_TOP) && (j == 0);
    float invev[8];
    if (do_ot) {
        const float* ip = g_inve0 + (size_t)t * NE;
        *(float4*)&invev[0] = *(const float4*)&ip[colb];
        *(float4*)&invev[4] = *(const float4*)&ip[colb + 4];
    }

    #pragma unroll
    for (int r = 0; r < 8; ++r) {
        int row = rg8 + r;
        int l = rowbase + row;

        float gv[8];
        #pragma unroll
        for (int p = 0; p < 4; ++p)
            asm("mov.b64 {%0,%1}, %2;" : "=f"(gv[2*p]), "=f"(gv[2*p+1]) : "l"(acc[r][p]));

        float bv = 3.4e38f; int bi = NE;
        #pragma unroll
        for (int c = 0; c < 8; ++c) {
            float v = fmaf(-2.f, gv[c], e2v[c]);
            if (v < bv || (v == bv && colb + c < bi)) { bv = v; bi = colb + c; }
        }
        #pragma unroll
        for (int o = 1; o <= 4; o <<= 1) {
            float ov = __shfl_xor_sync(0xffffffffu, bv, o);
            int   oi = __shfl_xor_sync(0xffffffffu, bi, o);
            if (ov < bv || (ov == bv && oi < bi)) { bv = ov; bi = oi; }
        }
        if (co == 0 && l < L) { ep->minv[w][row] = bv; ep->mini[w][row] = bi; }

        if (do_ot) {
            float m = -3.4e38f;
            #pragma unroll
            for (int c = 0; c < 8; ++c) m = fmaxf(m, gv[c] * INV512);
            #pragma unroll
            for (int o = 1; o <= 4; o <<= 1)
                m = fmaxf(m, __shfl_xor_sync(0xffffffffu, m, o));
            float Z = 0.f, Tt = 0.f;
            #pragma unroll
            for (int c = 0; c < 8; ++c) {
                float pe = expf(gv[c] * INV512 - m);
                Z += pe;  Tt += gv[c] * invev[c] * pe;
            }
            #pragma unroll
            for (int o = 1; o <= 4; o <<= 1) {
                Z  += __shfl_xor_sync(0xffffffffu, Z,  o);
                Tt += __shfl_xor_sync(0xffffffffu, Tt, o);
            }
            if (co == 0 && l < L) { ep->otm[w][row] = m; ep->otz[w][row] = Z; ep->ott[w][row] = Tt; }
        }
    }
    __syncthreads();

    // combine the 8 warp (col-band) partials per row; s2 from staged x
    if (tid < BM) {
        int row = tid, l = rowbase + row;
        if (l < L) {
            float s2 = 0.f;
            #pragma unroll 8
            for (int c = 0; c < KDIM; ++c) { float v = x_s[c*BM + row]; s2 += v*v; }
            float bv = ep->minv[0][row]; int bi = ep->mini[0][row];
            #pragma unroll
            for (int ww = 1; ww < 8; ++ww) {
                float v = ep->minv[ww][row];
                if (v < bv) { bv = v; bi = ep->mini[ww][row]; }
            }
            ep->ind[row]  = bi;
            ep->dist[row] = s2 + bv;
            if (!IS_TOP)
                out[ID_OFF + ((size_t)s*B + b)*L + l] = (float)bi;
            if (do_ot) {
                float m = ep->otm[0][row];
                #pragma unroll
                for (int ww = 1; ww < 8; ++ww) m = fmaxf(m, ep->otm[ww][row]);
                float Z = 0.f, Tt = 0.f;
                #pragma unroll
                for (int ww = 0; ww < 8; ++ww) {
                    float sc = expf(ep->otm[ww][row] - m);
                    Z  += ep->otz[ww][row] * sc;
                    Tt += ep->ott[ww][row] * sc;
                }
                float invx = 1.0f / (sqrtf(s2) + EPSF);
                out[OT_OFF + (size_t)b*L + l] = (Z - invx * Tt) / Z;
            }
        }
    }
    __syncthreads();

    if (tid == 0) {
        int nval = L - rowbase; if (nval > BM) nval = BM;
        float sum = 0.f;
        for (int r = 0; r < nval; ++r) sum += ep->dist[r];
        atomicAdd(&out[DIFF_OFF], sum * (1.0f / (float)(L * KDIM)));
    }

    // gather quantized codes from transposed book (coalesced rows)
    const int OD = IS_TOP ? DTOP : DLOW;
    const float* embT = IS_TOP ? (g_embT_top + (size_t)t * NE * DTOP)
                               : (g_embT_lvl + ((size_t)j * NBOOK + t) * NE * DLOW);
    for (int it = tid; it < BM*OD; it += NTHREADS) {
        int r = it / OD, c = it % OD;
        int l = rowbase + r;
        if (l >= L) continue;
        float v = embT[(size_t)ep->ind[r] * OD + c];
        if (IS_TOP)
            g_q4[((size_t)b*L + l)*DTOP + c] = v;
        else
            out[QUANT_OFF + (((size_t)s*B + b)*L + l)*DLOW + c] = v;
    }
#undef FILL_E
#undef COMPUTE
}

extern "C" void kernel_launch(void* const* d_in, const int* in_sizes, int n_in,
                              void* d_out, int out_size)
{
    const float* input_list = nullptr;
    const float* cb_top     = nullptr;
    const float* cb_lvl     = nullptr;
    const int*   label      = nullptr;

    for (int i = 0; i < n_in; ++i) {
        switch (in_sizes[i]) {
            case 8028160: input_list = (const float*)d_in[i]; break;
            case 491520:  cb_top     = (const float*)d_in[i]; break;
            case 3932160: cb_lvl     = (const float*)d_in[i]; break;
            case 128:     label      = (const int*)  d_in[i]; break;
        }
    }
    if (!input_list || !cb_top || !cb_lvl || !label) return;

    float* out = (float*)d_out;

    norms_kernel<<<NBOOK + 4*NBOOK, NE>>>(cb_top, cb_lvl, out);
    transpose_kernel<<<dim3(NE/32, 4, NBOOK + 4*NBOOK), dim3(32, 8)>>>(cb_top, cb_lvl);
    vq_gemm<DTOP, true ><<<dim3(ROWBLOCKS, B, 1), NTHREADS>>>(input_list, cb_top, cb_lvl, label, out);
    vq_gemm<DLOW, false><<<dim3(ROWBLOCKS, B, 4), NTHREADS>>>(input_list, cb_top, cb_lvl, label, out);
}

// round 11
// speedup vs baseline: 1.4261x; 1.1620x over previous
#include <cuda_runtime.h>
#include <math.h>
#include <stdint.h>

#define B      128
#define L      196
#define DTOP   64
#define DLOW   128
#define NE     512
#define NBOOK  15
#define EPSF   1e-8f
#define INV512 (1.0f/512.0f)

#define BM        32
#define KT        8
#define KDIM      64
#define NTHREADS  256
#define ROWBLOCKS 7

#define QUANT_OFF 0ll
#define QUANT_CNT (4ll*B*L*DLOW)
#define DIFF_OFF  (QUANT_OFF + QUANT_CNT)
#define ID_OFF    (DIFF_OFF + 1)
#define ID_CNT    (4ll*B*L)
#define OT_OFF    (ID_OFF + ID_CNT)

__device__ int   g_ind4[B*L];
__device__ float g_e2_top[NBOOK*NE];
__device__ float g_e2_lvl[4*NBOOK*NE];
__device__ float g_inve0[NBOOK*NE];
__device__ float g_embT_top[NBOOK*NE*DTOP];
__device__ float g_embT_lvl[4*NBOOK*NE*DLOW];
__device__ float g_C[60ull*NE*NE];   // 60 books x 512 codes x 512 cols (63MB)

__device__ __forceinline__ unsigned smem_u32(const void* p) {
    unsigned r;
    asm("{.reg .u64 t; cvta.to.shared.u64 t, %1; cvt.u32.u64 %0, t;}" : "=r"(r) : "l"(p));
    return r;
}
__device__ __forceinline__ void cp16(unsigned dst, const void* src) {
    asm volatile("cp.async.cg.shared.global [%0], [%1], 16;" :: "r"(dst), "l"(src));
}
#define CP_COMMIT() asm volatile("cp.async.commit_group;" ::: "memory")
#define CP_WAIT0()  asm volatile("cp.async.wait_group 0;" ::: "memory")
#define CP_WAIT1()  asm volatile("cp.async.wait_group 1;" ::: "memory")
#define FMA2(a,x,e) asm("fma.rn.f32x2 %0, %1, %2, %0;" : "+l"(a) : "l"(x), "l"(e))

__global__ void norms_kernel(const float* __restrict__ cb_top,
                             const float* __restrict__ cb_lvl,
                             float* __restrict__ out)
{
    int k = threadIdx.x, book = blockIdx.x;
    if (book == 0 && k == 0) out[DIFF_OFF] = 0.0f;
    if (book < NBOOK) {
        const float* e = cb_top + (size_t)book * DTOP * NE;
        float s = 0.f;
        #pragma unroll 8
        for (int i = 0; i < DTOP; ++i) { float v = e[(size_t)i*NE + k]; s += v*v; }
        g_e2_top[book*NE + k] = s;
    } else {
        int bl = book - NBOOK;
        const float* e = cb_lvl + (size_t)bl * DLOW * NE;
        float s = 0.f;
        #pragma unroll 8
        for (int i = 0; i < DLOW; ++i) { float v = e[(size_t)i*NE + k]; s += v*v; }
        g_e2_lvl[bl*NE + k] = s;
        if (bl < NBOOK) g_inve0[bl*NE + k] = 1.0f / (sqrtf(s) + EPSF);
    }
}

__global__ void transpose_kernel(const float* __restrict__ cb_top,
                                 const float* __restrict__ cb_lvl)
{
    __shared__ float tile[32][33];
    int book = blockIdx.z;
    int k0 = blockIdx.x * 32, d0 = blockIdx.y * 32;
    const float* src; float* dst; int OD;
    if (book < NBOOK) {
        if (d0 >= DTOP) return;
        src = cb_top + (size_t)book * DTOP * NE;
        dst = g_embT_top + (size_t)book * NE * DTOP;  OD = DTOP;
    } else {
        int bl = book - NBOOK;
        src = cb_lvl + (size_t)bl * DLOW * NE;
        dst = g_embT_lvl + (size_t)bl * NE * DLOW;    OD = DLOW;
    }
    int tx = threadIdx.x, ty = threadIdx.y;
    #pragma unroll
    for (int dy = ty; dy < 32; dy += 8)
        tile[dy][tx] = src[(size_t)(d0 + dy) * NE + k0 + tx];
    __syncthreads();
    #pragma unroll
    for (int dy = ty; dy < 32; dy += 8)
        dst[(size_t)(k0 + dy) * OD + d0 + tx] = tile[tx][dy];
}

// shared mainloop macros (warp-private double-buffered e slice, sync-free)
#define FILL_E_IMPL(EMB, BUF, TILE)                                            \
do {                                                                           \
    const char* esrc = (const char*)((EMB) + (size_t)(TILE) * KT * NE + w*64); \
    const unsigned dstb = e_base + (unsigned)(w*2 + (BUF)) * 2048u;            \
    _Pragma("unroll")                                                          \
    for (int q = 0; q < 4; ++q) {                                              \
        int idx = lane + q*32;                                                 \
        int kk = idx >> 4, c16 = idx & 15;                                     \
        cp16(dstb + (unsigned)(kk*256 + c16*16),                               \
             esrc + (size_t)kk*2048 + (size_t)c16*16);                         \
    }                                                                          \
    CP_COMMIT();                                                               \
} while (0)

#define COMPUTE_IMPL(BUF)                                                      \
do {                                                                           \
    const char* ek = (const char*)e_s + (unsigned)(w*2 + (BUF))*2048u + co*32; \
    _Pragma("unroll")                                                          \
    for (int i = 0; i < KT; ++i) {                                             \
        ulonglong2 ea = *(const ulonglong2*)(ek + i*256);                      \
        ulonglong2 eb = *(const ulonglong2*)(ek + i*256 + 16);                 \
        float4 xa = *(const float4*)(xk + i*BM);                               \
        float4 xb = *(const float4*)(xk + i*BM + 4);                           \
        float xr8[8] = {xa.x, xa.y, xa.z, xa.w, xb.x, xb.y, xb.z, xb.w};       \
        _Pragma("unroll")                                                      \
        for (int r = 0; r < 8; ++r) {                                          \
            unsigned long long xp;                                             \
            asm("mov.b64 %0, {%1,%1};" : "=l"(xp) : "f"(xr8[r]));              \
            FMA2(acc[r][0], xp, ea.x); FMA2(acc[r][1], xp, ea.y);              \
            FMA2(acc[r][2], xp, eb.x); FMA2(acc[r][3], xp, eb.y);              \
        }                                                                      \
    }                                                                          \
    xk += KT*BM;                                                               \
} while (0)

// ---------------------------------------------------------------------------
// C table: C[book][m][n] = dot(etop_t[m], emb_lvl[book][64:128][n])
// grid(16, 60), 256 thr. Block = 32 m-rows x 512 cols, K=64.
// ---------------------------------------------------------------------------
__global__ __launch_bounds__(NTHREADS, 2)
void cpre_kernel(const float* __restrict__ cb_lvl)
{
    __shared__ __align__(16) float e_s[8*2*KT*64];  // 32 KB
    __shared__ __align__(16) float x_s[KDIM*BM];    // 8 KB

    const int mb   = blockIdx.x;        // 0..15
    const int book = blockIdx.y;        // 0..59
    const int t    = book % NBOOK;
    const int mbase = mb * BM;
    const int tid  = threadIdx.x;
    const int lane = tid & 31;
    const int w    = tid >> 5;
    const int rg8  = (lane >> 3) * 8;
    const int co   = lane & 7;
    const int colb = w * 64 + co * 8;

    const float* emb = cb_lvl + (size_t)book * DLOW * NE + (size_t)DTOP * NE;
    const unsigned e_base = smem_u32(e_s);

    unsigned long long acc[8][4];
    #pragma unroll
    for (int r = 0; r < 8; ++r)
        #pragma unroll
        for (int p = 0; p < 4; ++p) acc[r][p] = 0ull;

    FILL_E_IMPL(emb, 0, 0);
    // x = embT_top[t] rows mbase..mbase+31 (each 64 floats)
    for (int it = tid; it < BM*KDIM; it += NTHREADS) {
        int row = it >> 6, c = it & 63;
        x_s[c*BM + row] = g_embT_top[((size_t)t*NE + mbase + row)*DTOP + c];
    }
    __syncthreads();

    const float* xk = x_s + rg8;
    #pragma unroll
    for (int tt = 0; tt < KDIM/KT; ++tt) {
        if (tt + 1 < KDIM/KT) { FILL_E_IMPL(emb, (tt + 1) & 1, tt + 1); CP_WAIT1(); }
        else                  { CP_WAIT0(); }
        COMPUTE_IMPL(tt & 1);
    }

    #pragma unroll
    for (int r = 0; r < 8; ++r) {
        int m = mbase + rg8 + r;
        float gv[8];
        #pragma unroll
        for (int p = 0; p < 4; ++p)
            asm("mov.b64 {%0,%1}, %2;" : "=f"(gv[2*p]), "=f"(gv[2*p+1]) : "l"(acc[r][p]));
        float* dst = g_C + ((size_t)book*NE + m)*NE + colb;
        *(float4*)dst       = make_float4(gv[0], gv[1], gv[2], gv[3]);
        *(float4*)(dst + 4) = make_float4(gv[4], gv[5], gv[6], gv[7]);
    }
}

struct Epi {
    float minv[8][BM]; int mini[8][BM];
    float otm[8][BM], otz[8][BM], ott[8][BM];
    int ind[BM]; float dist[BM];
};

// ---------------------------------------------------------------------------
// Unified VQ kernel, K=64 for both top and lower levels.
// Top: x = input_list[4]; stores g_ind4 + diff. Lower: x = input_list[j];
// gv corrected by C[ind4] row; full outputs.
// ---------------------------------------------------------------------------
template<bool IS_TOP>
__launch_bounds__(NTHREADS, 2)
__global__ void vq_gemm(const float* __restrict__ input_list,
                        const float* __restrict__ cb_top,
                        const float* __restrict__ cb_lvl,
                        const int*   __restrict__ label,
                        float*       __restrict__ out)
{
    __shared__ __align__(16) float e_s[8*2*KT*64];  // 32 KB
    __shared__ __align__(16) float x_s[KDIM*BM];    // 8 KB
    __shared__ int ind4s[BM];

    const int rb = blockIdx.x;
    const int b  = blockIdx.y;
    const int s  = blockIdx.z;
    const int j  = IS_TOP ? 4 : (3 - s);
    const int t  = label[b];
    const int book = j * NBOOK + t;     // lower only
    const int rowbase = rb * BM;
    const int tid  = threadIdx.x;
    const int lane = tid & 31;
    const int w    = tid >> 5;
    const int rg8  = (lane >> 3) * 8;
    const int co   = lane & 7;
    const int colb = w * 64 + co * 8;

    const float* emb = IS_TOP ? (cb_top + (size_t)t * DTOP * NE)
                              : (cb_lvl + (size_t)book * DLOW * NE);
    const unsigned e_base = smem_u32(e_s);

    unsigned long long acc[8][4];
    #pragma unroll
    for (int r = 0; r < 8; ++r)
        #pragma unroll
        for (int p = 0; p < 4; ++p) acc[r][p] = 0ull;

    FILL_E_IMPL(emb, 0, 0);
    {   // stage x (64 floats per row; pad rows zero) + ind4
        const float* xin = input_list + (((size_t)j*B + b)*L)*DTOP;
        for (int it = tid; it < BM*KDIM; it += NTHREADS) {
            int row = it >> 6, c = it & 63;
            int l = rowbase + row;
            x_s[c*BM + row] = (l < L) ? xin[(size_t)l*DTOP + c] : 0.f;
        }
        if (!IS_TOP && tid < BM) {
            int l = rowbase + tid;
            ind4s[tid] = (l < L) ? g_ind4[(size_t)b*L + l] : 0;
        }
    }
    __syncthreads();

    const float* xk = x_s + rg8;
    #pragma unroll
    for (int tt = 0; tt < KDIM/KT; ++tt) {
        if (tt + 1 < KDIM/KT) { FILL_E_IMPL(emb, (tt + 1) & 1, tt + 1); CP_WAIT1(); }
        else                  { CP_WAIT0(); }
        COMPUTE_IMPL(tt & 1);
    }
    __syncthreads();   // e_s dead -> alias epilogue

    Epi* ep = (Epi*)e_s;
    const float* e2p = IS_TOP ? (g_e2_top + (size_t)t * NE)
                              : (g_e2_lvl + (size_t)book * NE);
    float e2v[8];
    *(float4*)&e2v[0] = *(const float4*)&e2p[colb];
    *(float4*)&e2v[4] = *(const float4*)&e2p[colb + 4];
    const bool do_ot = (!IS_TOP) && (j == 0);
    float invev[8];
    if (do_ot) {
        const float* ip = g_inve0 + (size_t)t * NE;
        *(float4*)&invev[0] = *(const float4*)&ip[colb];
        *(float4*)&invev[4] = *(const float4*)&ip[colb + 4];
    }

    #pragma unroll
    for (int r = 0; r < 8; ++r) {
        int row = rg8 + r;
        int l = rowbase + row;

        float gv[8];
        #pragma unroll
        for (int p = 0; p < 4; ++p)
            asm("mov.b64 {%0,%1}, %2;" : "=f"(gv[2*p]), "=f"(gv[2*p+1]) : "l"(acc[r][p]));

        if (!IS_TOP) {   // add precomputed q4 contribution
            const float* Cp = g_C + ((size_t)book*NE + ind4s[row])*NE + colb;
            float4 c0 = *(const float4*)Cp;
            float4 c1 = *(const float4*)(Cp + 4);
            gv[0] += c0.x; gv[1] += c0.y; gv[2] += c0.z; gv[3] += c0.w;
            gv[4] += c1.x; gv[5] += c1.y; gv[6] += c1.z; gv[7] += c1.w;
        }

        float bv = 3.4e38f; int bi = NE;
        #pragma unroll
        for (int c = 0; c < 8; ++c) {
            float v = fmaf(-2.f, gv[c], e2v[c]);
            if (v < bv || (v == bv && colb + c < bi)) { bv = v; bi = colb + c; }
        }
        #pragma unroll
        for (int o = 1; o <= 4; o <<= 1) {
            float ov = __shfl_xor_sync(0xffffffffu, bv, o);
            int   oi = __shfl_xor_sync(0xffffffffu, bi, o);
            if (ov < bv || (ov == bv && oi < bi)) { bv = ov; bi = oi; }
        }
        if (co == 0 && l < L) { ep->minv[w][row] = bv; ep->mini[w][row] = bi; }

        if (do_ot) {
            float m = -3.4e38f;
            #pragma unroll
            for (int c = 0; c < 8; ++c) m = fmaxf(m, gv[c] * INV512);
            #pragma unroll
            for (int o = 1; o <= 4; o <<= 1)
                m = fmaxf(m, __shfl_xor_sync(0xffffffffu, m, o));
            float Z = 0.f, Tt = 0.f;
            #pragma unroll
            for (int c = 0; c < 8; ++c) {
                float pe = expf(gv[c] * INV512 - m);
                Z += pe;  Tt += gv[c] * invev[c] * pe;
            }
            #pragma unroll
            for (int o = 1; o <= 4; o <<= 1) {
                Z  += __shfl_xor_sync(0xffffffffu, Z,  o);
                Tt += __shfl_xor_sync(0xffffffffu, Tt, o);
            }
            if (co == 0 && l < L) { ep->otm[w][row] = m; ep->otz[w][row] = Z; ep->ott[w][row] = Tt; }
        }
    }
    __syncthreads();

    if (tid < BM) {
        int row = tid, l = rowbase + row;
        if (l < L) {
            float s2 = 0.f;
            #pragma unroll 8
            for (int c = 0; c < KDIM; ++c) { float v = x_s[c*BM + row]; s2 += v*v; }
            if (!IS_TOP) s2 += g_e2_top[(size_t)t*NE + ind4s[row]];  // |q4|^2
            float bv = ep->minv[0][row]; int bi = ep->mini[0][row];
            #pragma unroll
            for (int ww = 1; ww < 8; ++ww) {
                float v = ep->minv[ww][row];
                if (v < bv) { bv = v; bi = ep->mini[ww][row]; }
            }
            ep->ind[row]  = bi;
            ep->dist[row] = s2 + bv;
            if (IS_TOP)
                g_ind4[(size_t)b*L + l] = bi;
            else
                out[ID_OFF + ((size_t)s*B + b)*L + l] = (float)bi;
            if (do_ot) {
                float m = ep->otm[0][row];
                #pragma unroll
                for (int ww = 1; ww < 8; ++ww) m = fmaxf(m, ep->otm[ww][row]);
                float Z = 0.f, Tt = 0.f;
                #pragma unroll
                for (int ww = 0; ww < 8; ++ww) {
                    float sc = expf(ep->otm[ww][row] - m);
                    Z  += ep->otz[ww][row] * sc;
                    Tt += ep->ott[ww][row] * sc;
                }
                float invx = 1.0f / (sqrtf(s2) + EPSF);
                out[OT_OFF + (size_t)b*L + l] = (Z - invx * Tt) / Z;
            }
        }
    }
    __syncthreads();

    if (tid == 0) {
        int nval = L - rowbase; if (nval > BM) nval = BM;
        float sum = 0.f;
        for (int r = 0; r < nval; ++r) sum += ep->dist[r];
        const float div = IS_TOP ? (1.0f / (float)(L * DTOP)) : (1.0f / (float)(L * DLOW));
        atomicAdd(&out[DIFF_OFF], sum * div);
    }

    if (!IS_TOP) {  // gather quantized codes (coalesced)
        const float* embT = g_embT_lvl + (size_t)book * NE * DLOW;
        for (int it = tid; it < BM*DLOW; it += NTHREADS) {
            int r = it >> 7, c = it & 127;
            int l = rowbase + r;
            if (l >= L) continue;
            out[QUANT_OFF + (((size_t)s*B + b)*L + l)*DLOW + c] =
                embT[(size_t)ep->ind[r] * DLOW + c];
        }
    }
}

extern "C" void kernel_launch(void* const* d_in, const int* in_sizes, int n_in,
                              void* d_out, int out_size)
{
    const float* input_list = nullptr;
    const float* cb_top     = nullptr;
    const float* cb_lvl     = nullptr;
    const int*   label      = nullptr;

    for (int i = 0; i < n_in; ++i) {
        switch (in_sizes[i]) {
            case 8028160: input_list = (const float*)d_in[i]; break;
            case 491520:  cb_top     = (const float*)d_in[i]; break;
            case 3932160: cb_lvl     = (const float*)d_in[i]; break;
            case 128:     label      = (const int*)  d_in[i]; break;
        }
    }
    if (!input_list || !cb_top || !cb_lvl || !label) return;

    float* out = (float*)d_out;

    norms_kernel<<<NBOOK + 4*NBOOK, NE>>>(cb_top, cb_lvl, out);
    transpose_kernel<<<dim3(NE/32, 4, NBOOK + 4*NBOOK), dim3(32, 8)>>>(cb_top, cb_lvl);
    cpre_kernel<<<dim3(16, 60), NTHREADS>>>(cb_lvl);
    vq_gemm<true ><<<dim3(ROWBLOCKS, B),    NTHREADS>>>(input_list, cb_top, cb_lvl, label, out);
    vq_gemm<false><<<dim3(ROWBLOCKS, B, 4), NTHREADS>>>(input_list, cb_top, cb_lvl, label, out);
}